// round 14
// baseline (speedup 1.0000x reference)
#include <cuda_runtime.h>
#include <cuda_fp8.h>
#include <cstdint>

#define F_ 16
#define B_ 4096
#define D_ 256
#define K_ 1024
#define WSCALE 64.0f
#define GATEU  40.0f   // scaled units = 0.625 true ≈ 12 sigma of fp8 screen noise

// ---------------- device scratch (allocation-free) ----------------
__device__ __align__(128) float   g_wt [F_ * K_ * D_];   // w^T fp32 [f][k][d]
__device__ __align__(128) uint8_t g_w8 [F_ * K_ * D_];   // (64*w)^T e4m3 [f][k][d]
__device__ __align__(128) uint8_t g_x8 [F_ * B_ * D_];   // x e4m3 [f][b][d]
__device__ float    g_wsq [F_ * K_];        // ||w_k||^2 (unscaled)
__device__ uint32_t g_ckey[F_ * B_ * 192];  // packed (64*score, code) keys, 24/tile
__device__ float    g_part[8192];           // loss partials

// ---------------- PTX helpers ----------------
__device__ __forceinline__ uint32_t sm_u32(const void* p) {
    uint32_t a;
    asm("{ .reg .u64 t; cvta.to.shared.u64 t, %1; cvt.u32.u64 %0, t; }" : "=r"(a) : "l"(p));
    return a;
}
__device__ __forceinline__ void cp16(uint32_t saddr, const void* g) {
    asm volatile("cp.async.cg.shared.global [%0], [%1], 16;" :: "r"(saddr), "l"(g));
}
__device__ __forceinline__ void ldsm4(uint32_t* r, uint32_t a) {
    asm volatile("ldmatrix.sync.aligned.m8n8.x4.shared.b16 {%0,%1,%2,%3}, [%4];"
                 : "=r"(r[0]), "=r"(r[1]), "=r"(r[2]), "=r"(r[3]) : "r"(a));
}
__device__ __forceinline__ void mma16832(float* c, const uint32_t* a, const uint32_t* b) {
    asm volatile(
        "mma.sync.aligned.m16n8k32.row.col.f32.e4m3.e4m3.f32 "
        "{%0,%1,%2,%3}, {%4,%5,%6,%7}, {%8,%9}, {%0,%1,%2,%3};"
        : "+f"(c[0]), "+f"(c[1]), "+f"(c[2]), "+f"(c[3])
        : "r"(a[0]), "r"(a[1]), "r"(a[2]), "r"(a[3]), "r"(b[0]), "r"(b[1]));
}
// ---- packed (score, index) keys: monotonic float->u32, low 10 bits = code idx ----
__device__ __forceinline__ uint32_t packkey(float v, int kk) {
    uint32_t s = __float_as_uint(v);
    uint32_t u = s ^ ((uint32_t)((int)s >> 31) | 0x80000000u);
    return (u & 0xFFFFFC00u) | (uint32_t)kk;
}
__device__ __forceinline__ float unpackval(uint32_t key) {
    uint32_t u = key & 0xFFFFFC00u;
    uint32_t s = (u & 0x80000000u) ? (u ^ 0x80000000u) : ~u;
    return __uint_as_float(s);
}
// branchless sorted top-3 insert (ascending): 5 u32 min/max
__device__ __forceinline__ void kins3(uint32_t k, uint32_t& t0, uint32_t& t1, uint32_t& t2) {
    uint32_t m0 = max(t0, k); t0 = min(t0, k);
    uint32_t m1 = max(t1, m0); t1 = min(t1, m0);
    t2 = min(t2, m1);
}

// ---------------- kernel 1: fused prep (zones: x->fp8 | transpose | wsq) ----------------
#define NB_X 2048
#define NB_T 4096
#define NB_W 64
__global__ void k_prep(const float* __restrict__ x, const float* __restrict__ w) {
    const int bid = blockIdx.x, tid = threadIdx.x;
    if (bid < NB_X) {                         // zone X: x fp32 -> e4m3 (unscaled)
        int base = bid * 256 + tid;
#pragma unroll
        for (int i = 0; i < 8; i++) {
            int e = base + i * (NB_X * 256);  // float4 index < 4.19M
            float4 v = reinterpret_cast<const float4*>(x)[e];
            uint32_t lo = (uint32_t)__nv_cvt_float2_to_fp8x2(make_float2(v.x, v.y),
                                                             __NV_SATFINITE, __NV_E4M3);
            uint32_t hi = (uint32_t)__nv_cvt_float2_to_fp8x2(make_float2(v.z, v.w),
                                                             __NV_SATFINITE, __NV_E4M3);
            reinterpret_cast<uint32_t*>(g_x8)[e] = lo | (hi << 16);
        }
    } else if (bid < NB_X + NB_T) {           // zone T: w[f][d][k] -> wt fp32 + 64w e4m3
        __shared__ float t[32][33];
        int tb = bid - NB_X;
        int f = tb >> 8, rem = tb & 255;
        int k0 = (rem & 31) * 32, d0 = (rem >> 5) * 32;
        int tx = tid & 31, ty = tid >> 5;     // 32 x 8
        const float* wf = w + (size_t)f * D_ * K_;
#pragma unroll
        for (int i = 0; i < 4; i++) {
            int d = d0 + ty + i * 8;
            t[ty + i * 8][tx] = wf[(size_t)d * K_ + k0 + tx];
        }
        __syncthreads();
        float*   wtf = g_wt + (size_t)f * K_ * D_;
        uint8_t* w8f = g_w8 + (size_t)f * K_ * D_;
#pragma unroll
        for (int i = 0; i < 4; i++) {
            int k = k0 + ty + i * 8;
            float v = t[tx][ty + i * 8];
            wtf[(size_t)k * D_ + d0 + tx] = v;
            w8f[(size_t)k * D_ + d0 + tx] =
                (uint8_t)__nv_cvt_float_to_fp8(v * WSCALE, __NV_SATFINITE, __NV_E4M3);
        }
    } else {                                  // zone W: wsq
        int tt = (bid - NB_X - NB_T) * 256 + tid;   // 0..16383
        int f = tt >> 10, k = tt & (K_ - 1);
        const float* p = w + (size_t)f * D_ * K_ + k;
        float s = 0.f;
#pragma unroll 8
        for (int d = 0; d < D_; d++) {
            float v = p[(size_t)d * K_];
            s = fmaf(v, v, s);
        }
        g_wsq[tt] = s;
    }
}

// ---------------- kernel 2: e4m3 mma screen, per-thread top-3 ----------------
// Grid (B/128, K/128, F). Block 256 (8 warps, 4x2 grid, warp tile 32x64).
// 2 CTAs/SM. Scores 64*(wsq - 2 x.w) over D=256 in 2 chunks of 128 fp8 (128B
// rows), both prefetched via cp.async. fp8 k32 mma has the SAME frag/ldsm
// shape as bf16 k16 -> identical swizzle & addressing, half the mma count.
// Epilogue: per-thread packed-key top-3 of its 16 codes, stored directly.
// Per row, 8 threads own codes (tg x wn) -> 24 keys/row/tile, 192/row total.
__global__ void __launch_bounds__(256, 2) k_screen() {
    extern __shared__ __align__(128) char dsm[];
    __shared__ float s_wsq[128];

    const int tid = threadIdx.x, lane = tid & 31, wid = tid >> 5;
    const int wm = wid >> 1, wn = wid & 1;
    const int g = lane >> 2, tg = lane & 3;
    const int f = blockIdx.z, kt = blockIdx.y, row0 = blockIdx.x * 128;

    const uint32_t base = (sm_u32(dsm) + 1023u) & ~1023u;  // 2 x (A 16KB + B 16KB)

    if (tid < 128) s_wsq[tid] = WSCALE * g_wsq[f * K_ + kt * 128 + tid];

    const char* xg = (const char*)g_x8 + (size_t)(f * B_ + row0)     * 256;
    const char* wg = (const char*)g_w8 + (size_t)(f * K_ + kt * 128) * 256;

    auto issue = [&](int c) {
        uint32_t ab = base + (uint32_t)c * 32768u;
        uint32_t bb = ab + 16384u;
#pragma unroll
        for (int i = 0; i < 4; i++) {                    // A: 1024 x 16B
            int t = tid + i * 256, r = t >> 3, cc = t & 7;
            cp16(ab + (uint32_t)(r * 128 + ((cc * 16) ^ ((r & 7) << 4))),
                 xg + (size_t)r * 256 + c * 128 + cc * 16);
        }
#pragma unroll
        for (int i = 0; i < 4; i++) {                    // B: 1024 x 16B
            int t = tid + i * 256, r = t >> 3, cc = t & 7;
            cp16(bb + (uint32_t)(r * 128 + ((cc * 16) ^ ((r & 7) << 4))),
                 wg + (size_t)r * 256 + c * 128 + cc * 16);
        }
        asm volatile("cp.async.commit_group;");
    };

    issue(0);
    issue(1);

    // per-lane ldmatrix constants: addr = base + rowBase + ((klb + laneCol) ^ rowSw)
    uint32_t aBase[2], aSw[2], bBase[4], bSw[4];
    const uint32_t aCol = (uint32_t)((lane >> 4) << 4);          // 0 | 16
    const uint32_t bCol = (uint32_t)(((lane >> 3) & 1) << 4);    // 0 | 16
#pragma unroll
    for (int mt = 0; mt < 2; mt++) {
        int r = wm * 32 + mt * 16 + (lane & 15);
        aBase[mt] = (uint32_t)(r * 128);
        aSw[mt]   = (uint32_t)((r & 7) << 4);
    }
#pragma unroll
    for (int nt2 = 0; nt2 < 4; nt2++) {
        int r = wn * 64 + nt2 * 16 + (lane & 7) + ((lane >> 4) << 3);
        bBase[nt2] = (uint32_t)(r * 128);
        bSw[nt2]   = (uint32_t)((r & 7) << 4);
    }

    float acc[2][8][4];
#pragma unroll
    for (int mt = 0; mt < 2; mt++)
#pragma unroll
        for (int nt = 0; nt < 8; nt++)
#pragma unroll
            for (int j = 0; j < 4; j++) acc[mt][nt][j] = 0.f;

#pragma unroll
    for (int c = 0; c < 2; c++) {
        if (c == 0) asm volatile("cp.async.wait_group 1;");
        else        asm volatile("cp.async.wait_group 0;");
        __syncthreads();
        uint32_t ab = base + (uint32_t)c * 32768u;
        uint32_t bb = ab + 16384u;
#pragma unroll
        for (int ks = 0; ks < 4; ks++) {                 // k32 per step, 128 fp8/chunk
            uint32_t klb = (uint32_t)(ks * 32);
            uint32_t a[2][4], b[4][4];
#pragma unroll
            for (int mt = 0; mt < 2; mt++)
                ldsm4(a[mt], ab + aBase[mt] + ((klb + aCol) ^ aSw[mt]));
#pragma unroll
            for (int nt2 = 0; nt2 < 4; nt2++)
                ldsm4(b[nt2], bb + bBase[nt2] + ((klb + bCol) ^ bSw[nt2]));
#pragma unroll
            for (int mt = 0; mt < 2; mt++)
#pragma unroll
                for (int nt2 = 0; nt2 < 4; nt2++) {
                    mma16832(acc[mt][nt2 * 2],     a[mt], &b[nt2][0]);
                    mma16832(acc[mt][nt2 * 2 + 1], a[mt], &b[nt2][2]);
                }
        }
    }

    // Epilogue: v = 64*wsq - 2*xw64 ; per-THREAD top-3 of its 16 codes per row.
    // Row rl is owned by 8 threads (tg in 0..3, wn in 0..1): slots (wn*4+tg)*3.
#pragma unroll
    for (int mt = 0; mt < 2; mt++)
#pragma unroll
        for (int h = 0; h < 2; h++) {
            uint32_t t0 = 0xFFFFFFFFu, t1 = 0xFFFFFFFFu, t2 = 0xFFFFFFFFu;
#pragma unroll
            for (int nt = 0; nt < 8; nt++)
#pragma unroll
                for (int e = 0; e < 2; e++) {
                    int cl = wn * 64 + nt * 8 + tg * 2 + e;
                    float v = fmaf(-2.f, acc[mt][nt][h * 2 + e], s_wsq[cl]);
                    kins3(packkey(v, kt * 128 + cl), t0, t1, t2);
                }
            int rl  = wm * 32 + mt * 16 + g + h * 8;
            int row = f * B_ + row0 + rl;
            uint32_t* dst = g_ckey + (size_t)row * 192 + kt * 24 + (wn * 4 + tg) * 3;
            dst[0] = t0; dst[1] = t1; dst[2] = t2;
        }
}

// ---------------- kernel 3: exact rescore + straight-through out + loss ----------------
// Warp per row; 192 candidate keys (6/lane). Gate at screened min + GATEU,
// ballot over passers, exact fp32 dot for each (expected ~3/row).
__global__ void __launch_bounds__(256) k_rescore(const float* __restrict__ x,
                                                 float* __restrict__ out) {
    __shared__ float red[8];
    const int tid = threadIdx.x, lane = tid & 31, wid = tid >> 5;
    const int row = blockIdx.x * 8 + wid;
    const int f = row >> 12;

    uint32_t k[6];
    {
        const uint32_t* kp = g_ckey + (size_t)row * 192 + lane * 6;
#pragma unroll
        for (int j = 0; j < 6; j++) k[j] = kp[j];
    }
    uint32_t kmin = k[0];
#pragma unroll
    for (int j = 1; j < 6; j++) kmin = min(kmin, k[j]);
#pragma unroll
    for (int o = 16; o >= 1; o >>= 1) kmin = min(kmin, __shfl_xor_sync(~0u, kmin, o));
    const uint32_t gthr = packkey(unpackval(kmin) + GATEU, 1023);

    const float4* x4 = reinterpret_cast<const float4*>(x + (size_t)row * D_);
    const float4 xa = x4[lane], xb2 = x4[lane + 32];

    float bs = 3.4e38f; int bi = 0;
#pragma unroll
    for (int j = 0; j < 6; j++) {
        unsigned m = __ballot_sync(~0u, k[j] <= gthr);
        while (m) {
            int src = __ffs(m) - 1;
            m &= m - 1;
            uint32_t kk = __shfl_sync(~0u, k[j], src);
            int ij = (int)(kk & 1023u);
            const float4* q4 = reinterpret_cast<const float4*>(g_wt + (size_t)(f * K_ + ij) * D_);
            float4 qa = q4[lane], qb = q4[lane + 32];
            float p = xa.x * qa.x;
            p = fmaf(xa.y, qa.y, p);  p = fmaf(xa.z, qa.z, p);  p = fmaf(xa.w, qa.w, p);
            p = fmaf(xb2.x, qb.x, p); p = fmaf(xb2.y, qb.y, p);
            p = fmaf(xb2.z, qb.z, p); p = fmaf(xb2.w, qb.w, p);
#pragma unroll
            for (int o = 16; o >= 1; o >>= 1) p += __shfl_xor_sync(~0u, p, o);
            float s = fmaf(-2.f, p, g_wsq[f * K_ + ij]);
            if (s < bs || (s == bs && ij < bi)) { bs = s; bi = ij; }   // first-index tie rule
        }
    }

    const float4* q4 = reinterpret_cast<const float4*>(g_wt + (size_t)(f * K_ + bi) * D_);
    float ls = 0.f;
    {
        float4 q = q4[lane];
        float d0 = q.x - xa.x, d1 = q.y - xa.y, d2 = q.z - xa.z, d3 = q.w - xa.w;
        float4 o; o.x = xa.x + d0; o.y = xa.y + d1; o.z = xa.z + d2; o.w = xa.w + d3;
        reinterpret_cast<float4*>(out)[(size_t)row * 64 + lane] = o;
        ls += d0 * d0 + d1 * d1 + d2 * d2 + d3 * d3;
    }
    {
        float4 q = q4[lane + 32];
        float d0 = q.x - xb2.x, d1 = q.y - xb2.y, d2 = q.z - xb2.z, d3 = q.w - xb2.w;
        float4 o; o.x = xb2.x + d0; o.y = xb2.y + d1; o.z = xb2.z + d2; o.w = xb2.w + d3;
        reinterpret_cast<float4*>(out)[(size_t)row * 64 + lane + 32] = o;
        ls += d0 * d0 + d1 * d1 + d2 * d2 + d3 * d3;
    }
#pragma unroll
    for (int o = 16; o >= 1; o >>= 1) ls += __shfl_xor_sync(~0u, ls, o);
    if (lane == 0) red[wid] = ls;
    __syncthreads();
    if (tid == 0) {
        float s = 0.f;
#pragma unroll
        for (int i = 0; i < 8; i++) s += red[i];
        g_part[blockIdx.x] = s;
    }
}

// ---------------- kernel 4: deterministic final loss ----------------
__global__ void k_loss(float* __restrict__ out) {
    __shared__ float red[256];
    const int tid = threadIdx.x;
    float s = 0.f;
#pragma unroll
    for (int i = 0; i < 32; i++) s += g_part[tid + 256 * i];
    red[tid] = s;
    __syncthreads();
    for (int st = 128; st > 0; st >>= 1) {
        if (tid < st) red[tid] += red[tid + st];
        __syncthreads();
    }
    if (tid == 0)
        out[(size_t)F_ * B_ * D_] = red[0] * (0.25f / (float)(F_ * B_ * D_));
}

extern "C" void kernel_launch(void* const* d_in, const int* in_sizes, int n_in,
                              void* d_out, int out_size) {
    const float* x = (const float*)d_in[0];   // [F,B,D] fp32
    const float* w = (const float*)d_in[1];   // [F,D,K] fp32
    float* out = (float*)d_out;
    (void)in_sizes; (void)n_in; (void)out_size;

    k_prep<<<NB_X + NB_T + NB_W, 256>>>(x, w);

    cudaFuncSetAttribute(k_screen, cudaFuncAttributeMaxDynamicSharedMemorySize, 66560);
    k_screen<<<dim3(B_ / 128, K_ / 128, F_), 256, 66560>>>();

    k_rescore<<<(F_ * B_) / 8, 256>>>(x, out);
    k_loss<<<1, 256>>>(out);
}

// round 15
// speedup vs baseline: 1.1989x; 1.1989x over previous
#include <cuda_runtime.h>
#include <cuda_bf16.h>
#include <cstdint>

#define F_ 16
#define B_ 4096
#define D_ 256
#define K_ 1024
#define GATEU 0.05f   // ~10 sigma of bf16 screen noise (+ key quantization 0.03)

// ---------------- device scratch (allocation-free) ----------------
__device__ __align__(128) float         g_wt [F_ * K_ * D_];   // w^T fp32 [f][k][d]
__device__ __align__(128) __nv_bfloat16 g_wtb[F_ * K_ * D_];   // w^T bf16 [f][k][d]
__device__ __align__(128) __nv_bfloat16 g_xb [F_ * B_ * D_];   // x bf16   [f][b][d]
__device__ float    g_wsq [F_ * K_];        // ||w_k||^2
__device__ uint32_t g_ckey[F_ * B_ * 192];  // packed (score, code) keys, 24/tile
__device__ float    g_part[8192];           // loss partials

// ---------------- PTX helpers ----------------
__device__ __forceinline__ uint32_t sm_u32(const void* p) {
    uint32_t a;
    asm("{ .reg .u64 t; cvta.to.shared.u64 t, %1; cvt.u32.u64 %0, t; }" : "=r"(a) : "l"(p));
    return a;
}
__device__ __forceinline__ void cp16(uint32_t saddr, const void* g) {
    asm volatile("cp.async.cg.shared.global [%0], [%1], 16;" :: "r"(saddr), "l"(g));
}
__device__ __forceinline__ void ldsm4(uint32_t* r, uint32_t a) {
    asm volatile("ldmatrix.sync.aligned.m8n8.x4.shared.b16 {%0,%1,%2,%3}, [%4];"
                 : "=r"(r[0]), "=r"(r[1]), "=r"(r[2]), "=r"(r[3]) : "r"(a));
}
__device__ __forceinline__ void mma16816(float* c, const uint32_t* a, const uint32_t* b) {
    asm volatile(
        "mma.sync.aligned.m16n8k16.row.col.f32.bf16.bf16.f32 "
        "{%0,%1,%2,%3}, {%4,%5,%6,%7}, {%8,%9}, {%0,%1,%2,%3};"
        : "+f"(c[0]), "+f"(c[1]), "+f"(c[2]), "+f"(c[3])
        : "r"(a[0]), "r"(a[1]), "r"(a[2]), "r"(a[3]), "r"(b[0]), "r"(b[1]));
}
// ---- packed (score, index) keys: monotonic float->u32, low 10 bits = code idx ----
__device__ __forceinline__ uint32_t packkey(float v, int kk) {
    uint32_t s = __float_as_uint(v);
    uint32_t u = s ^ ((uint32_t)((int)s >> 31) | 0x80000000u);
    return (u & 0xFFFFFC00u) | (uint32_t)kk;
}
__device__ __forceinline__ float unpackval(uint32_t key) {
    uint32_t u = key & 0xFFFFFC00u;
    uint32_t s = (u & 0x80000000u) ? (u ^ 0x80000000u) : ~u;
    return __uint_as_float(s);
}
// branchless sorted top-3 insert (ascending): 5 u32 min/max
__device__ __forceinline__ void kins3(uint32_t k, uint32_t& t0, uint32_t& t1, uint32_t& t2) {
    uint32_t m0 = max(t0, k); t0 = min(t0, k);
    uint32_t m1 = max(t1, m0); t1 = min(t1, m0);
    t2 = min(t2, m1);
}

// ---------------- kernel 1: fused prep (zones: x->bf16 | transpose | wsq) ----------------
#define NB_X 2048
#define NB_T 4096
#define NB_W 64
__global__ void k_prep(const float* __restrict__ x, const float* __restrict__ w) {
    const int bid = blockIdx.x, tid = threadIdx.x;
    if (bid < NB_X) {                         // zone X: x fp32 -> bf16
        int base = bid * 256 + tid;
#pragma unroll
        for (int i = 0; i < 8; i++) {
            int e = base + i * (NB_X * 256);  // float4 index < 4.19M
            float4 v = reinterpret_cast<const float4*>(x)[e];
            __nv_bfloat162 h0 = __floats2bfloat162_rn(v.x, v.y);
            __nv_bfloat162 h1 = __floats2bfloat162_rn(v.z, v.w);
            uint2 u;
            u.x = *reinterpret_cast<uint32_t*>(&h0);
            u.y = *reinterpret_cast<uint32_t*>(&h1);
            reinterpret_cast<uint2*>(g_xb)[e] = u;
        }
    } else if (bid < NB_X + NB_T) {           // zone T: w[f][d][k] -> wt fp32 + bf16
        __shared__ float t[32][33];
        int tb = bid - NB_X;
        int f = tb >> 8, rem = tb & 255;
        int k0 = (rem & 31) * 32, d0 = (rem >> 5) * 32;
        int tx = tid & 31, ty = tid >> 5;     // 32 x 8
        const float* wf = w + (size_t)f * D_ * K_;
#pragma unroll
        for (int i = 0; i < 4; i++) {
            int d = d0 + ty + i * 8;
            t[ty + i * 8][tx] = wf[(size_t)d * K_ + k0 + tx];
        }
        __syncthreads();
        float*         wtf  = g_wt  + (size_t)f * K_ * D_;
        __nv_bfloat16* wtbf = g_wtb + (size_t)f * K_ * D_;
#pragma unroll
        for (int i = 0; i < 4; i++) {
            int k = k0 + ty + i * 8;
            float v = t[tx][ty + i * 8];
            wtf [(size_t)k * D_ + d0 + tx] = v;
            wtbf[(size_t)k * D_ + d0 + tx] = __float2bfloat16(v);
        }
    } else {                                  // zone W: wsq (coalesced across k)
        int tt = (bid - NB_X - NB_T) * 256 + tid;   // 0..16383
        int f = tt >> 10, k = tt & (K_ - 1);
        const float* p = w + (size_t)f * D_ * K_ + k;
        float s = 0.f;
#pragma unroll 8
        for (int d = 0; d < D_; d++) {
            float v = p[(size_t)d * K_];
            s = fmaf(v, v, s);
        }
        g_wsq[tt] = s;
    }
}

// ---------------- kernel 2: bf16 mma.sync screen, per-thread top-3 ----------------
// Grid (B/128, K/128, F). Block 256 (8 warps, 4x2 grid, warp tile 32x64).
// 2 CTAs/SM. S[128][128] over K=D=256, 4 d-chunks of 64 bf16 (128B rows),
// 3-stage cp.async pipeline, ONE sync per chunk, issue-before-compute.
// Epilogue: per-thread packed-key top-3 of its 16 codes, stored directly.
// Per row, 8 owner threads (tg x wn) -> 24 keys/row/tile, 192/row total.
// SMEM swizzle: addr = r*128 + (colByte ^ ((r&7)<<4)).
__global__ void __launch_bounds__(256, 2) k_screen() {
    extern __shared__ __align__(128) char dsm[];
    __shared__ float s_wsq[128];

    const int tid = threadIdx.x, lane = tid & 31, wid = tid >> 5;
    const int wm = wid >> 1, wn = wid & 1;
    const int g = lane >> 2, tg = lane & 3;
    const int f = blockIdx.z, kt = blockIdx.y, row0 = blockIdx.x * 128;

    const uint32_t base = (sm_u32(dsm) + 1023u) & ~1023u;  // 3 x (A 16KB + B 16KB)

    if (tid < 128) s_wsq[tid] = g_wsq[f * K_ + kt * 128 + tid];

    const char* xg = (const char*)g_xb  + (size_t)(f * B_ + row0)      * 512;
    const char* wg = (const char*)g_wtb + (size_t)(f * K_ + kt * 128)  * 512;

    auto issue = [&](int c) {
        uint32_t ab = base + (uint32_t)(c % 3) * 32768u;
        uint32_t bb = ab + 16384u;
#pragma unroll
        for (int i = 0; i < 4; i++) {                    // A: 1024 x 16B
            int t = tid + i * 256, r = t >> 3, cc = t & 7;
            cp16(ab + (uint32_t)(r * 128 + ((cc * 16) ^ ((r & 7) << 4))),
                 xg + (size_t)r * 512 + c * 128 + cc * 16);
        }
#pragma unroll
        for (int i = 0; i < 4; i++) {                    // B: 1024 x 16B
            int t = tid + i * 256, r = t >> 3, cc = t & 7;
            cp16(bb + (uint32_t)(r * 128 + ((cc * 16) ^ ((r & 7) << 4))),
                 wg + (size_t)r * 512 + c * 128 + cc * 16);
        }
        asm volatile("cp.async.commit_group;");
    };

    issue(0);
    issue(1);

    // per-lane ldmatrix constants: addr = base + rowBase + ((klb + laneCol) ^ rowSw)
    uint32_t aBase[2], aSw[2], bBase[4], bSw[4];
    const uint32_t aCol = (uint32_t)((lane >> 4) << 4);          // 0 | 16
    const uint32_t bCol = (uint32_t)(((lane >> 3) & 1) << 4);    // 0 | 16
#pragma unroll
    for (int mt = 0; mt < 2; mt++) {
        int r = wm * 32 + mt * 16 + (lane & 15);
        aBase[mt] = (uint32_t)(r * 128);
        aSw[mt]   = (uint32_t)((r & 7) << 4);
    }
#pragma unroll
    for (int nt2 = 0; nt2 < 4; nt2++) {
        int r = wn * 64 + nt2 * 16 + (lane & 7) + ((lane >> 4) << 3);
        bBase[nt2] = (uint32_t)(r * 128);
        bSw[nt2]   = (uint32_t)((r & 7) << 4);
    }

    float acc[2][8][4];
#pragma unroll
    for (int mt = 0; mt < 2; mt++)
#pragma unroll
        for (int nt = 0; nt < 8; nt++)
#pragma unroll
            for (int j = 0; j < 4; j++) acc[mt][nt][j] = 0.f;

    for (int c = 0; c < 4; c++) {
        if (c == 3) asm volatile("cp.async.wait_group 0;");
        else        asm volatile("cp.async.wait_group 1;");
        __syncthreads();                                 // buffer c full for all warps
        if (c + 2 < 4) issue(c + 2);                     // buf (c+2)%3 consumed at c-1
        uint32_t ab = base + (uint32_t)(c % 3) * 32768u;
        uint32_t bb = ab + 16384u;
#pragma unroll
        for (int ks = 0; ks < 4; ks++) {
            uint32_t klb = (uint32_t)(ks * 32);          // k-step * 16 elems * 2B
            uint32_t a[2][4], b[4][4];
#pragma unroll
            for (int mt = 0; mt < 2; mt++)
                ldsm4(a[mt], ab + aBase[mt] + ((klb + aCol) ^ aSw[mt]));
#pragma unroll
            for (int nt2 = 0; nt2 < 4; nt2++)
                ldsm4(b[nt2], bb + bBase[nt2] + ((klb + bCol) ^ bSw[nt2]));
#pragma unroll
            for (int mt = 0; mt < 2; mt++)
#pragma unroll
                for (int nt2 = 0; nt2 < 4; nt2++) {
                    mma16816(acc[mt][nt2 * 2],     a[mt], &b[nt2][0]);
                    mma16816(acc[mt][nt2 * 2 + 1], a[mt], &b[nt2][2]);
                }
        }
    }

    // Epilogue: v = wsq - 2*xw ; per-THREAD top-3 of its 16 codes per row.
    // Row rl owned by 8 threads (tg in 0..3, wn in 0..1): slots (wn*4+tg)*3.
#pragma unroll
    for (int mt = 0; mt < 2; mt++)
#pragma unroll
        for (int h = 0; h < 2; h++) {
            uint32_t t0 = 0xFFFFFFFFu, t1 = 0xFFFFFFFFu, t2 = 0xFFFFFFFFu;
#pragma unroll
            for (int nt = 0; nt < 8; nt++)
#pragma unroll
                for (int e = 0; e < 2; e++) {
                    int cl = wn * 64 + nt * 8 + tg * 2 + e;
                    float v = fmaf(-2.f, acc[mt][nt][h * 2 + e], s_wsq[cl]);
                    kins3(packkey(v, kt * 128 + cl), t0, t1, t2);
                }
            int rl  = wm * 32 + mt * 16 + g + h * 8;
            int row = f * B_ + row0 + rl;
            uint32_t* dst = g_ckey + (size_t)row * 192 + kt * 24 + (wn * 4 + tg) * 3;
            dst[0] = t0; dst[1] = t1; dst[2] = t2;
        }
}

// ---------------- kernel 3: exact rescore + straight-through out + loss ----------------
// Warp per row; 192 candidate keys (6/lane). Gate at screened min + GATEU,
// ballot over passers, exact fp32 dot for each (expected ~1.3/row).
__global__ void __launch_bounds__(256) k_rescore(const float* __restrict__ x,
                                                 float* __restrict__ out) {
    __shared__ float red[8];
    const int tid = threadIdx.x, lane = tid & 31, wid = tid >> 5;
    const int row = blockIdx.x * 8 + wid;
    const int f = row >> 12;

    uint32_t k[6];
    {
        const uint32_t* kp = g_ckey + (size_t)row * 192 + lane * 6;
#pragma unroll
        for (int j = 0; j < 6; j++) k[j] = kp[j];
    }
    uint32_t kmin = k[0];
#pragma unroll
    for (int j = 1; j < 6; j++) kmin = min(kmin, k[j]);
#pragma unroll
    for (int o = 16; o >= 1; o >>= 1) kmin = min(kmin, __shfl_xor_sync(~0u, kmin, o));
    const uint32_t gthr = packkey(unpackval(kmin) + GATEU, 1023);

    const float4* x4 = reinterpret_cast<const float4*>(x + (size_t)row * D_);
    const float4 xa = x4[lane], xb2 = x4[lane + 32];

    float bs = 3.4e38f; int bi = 0;
#pragma unroll
    for (int j = 0; j < 6; j++) {
        unsigned m = __ballot_sync(~0u, k[j] <= gthr);
        while (m) {
            int src = __ffs(m) - 1;
            m &= m - 1;
            uint32_t kk = __shfl_sync(~0u, k[j], src);
            int ij = (int)(kk & 1023u);
            const float4* q4 = reinterpret_cast<const float4*>(g_wt + (size_t)(f * K_ + ij) * D_);
            float4 qa = q4[lane], qb = q4[lane + 32];
            float p = xa.x * qa.x;
            p = fmaf(xa.y, qa.y, p);  p = fmaf(xa.z, qa.z, p);  p = fmaf(xa.w, qa.w, p);
            p = fmaf(xb2.x, qb.x, p); p = fmaf(xb2.y, qb.y, p);
            p = fmaf(xb2.z, qb.z, p); p = fmaf(xb2.w, qb.w, p);
#pragma unroll
            for (int o = 16; o >= 1; o >>= 1) p += __shfl_xor_sync(~0u, p, o);
            float s = fmaf(-2.f, p, g_wsq[f * K_ + ij]);
            if (s < bs || (s == bs && ij < bi)) { bs = s; bi = ij; }   // first-index tie rule
        }
    }

    const float4* q4 = reinterpret_cast<const float4*>(g_wt + (size_t)(f * K_ + bi) * D_);
    float ls = 0.f;
    {
        float4 q = q4[lane];
        float d0 = q.x - xa.x, d1 = q.y - xa.y, d2 = q.z - xa.z, d3 = q.w - xa.w;
        float4 o; o.x = xa.x + d0; o.y = xa.y + d1; o.z = xa.z + d2; o.w = xa.w + d3;
        reinterpret_cast<float4*>(out)[(size_t)row * 64 + lane] = o;
        ls += d0 * d0 + d1 * d1 + d2 * d2 + d3 * d3;
    }
    {
        float4 q = q4[lane + 32];
        float d0 = q.x - xb2.x, d1 = q.y - xb2.y, d2 = q.z - xb2.z, d3 = q.w - xb2.w;
        float4 o; o.x = xb2.x + d0; o.y = xb2.y + d1; o.z = xb2.z + d2; o.w = xb2.w + d3;
        reinterpret_cast<float4*>(out)[(size_t)row * 64 + lane + 32] = o;
        ls += d0 * d0 + d1 * d1 + d2 * d2 + d3 * d3;
    }
#pragma unroll
    for (int o = 16; o >= 1; o >>= 1) ls += __shfl_xor_sync(~0u, ls, o);
    if (lane == 0) red[wid] = ls;
    __syncthreads();
    if (tid == 0) {
        float s = 0.f;
#pragma unroll
        for (int i = 0; i < 8; i++) s += red[i];
        g_part[blockIdx.x] = s;
    }
}

// ---------------- kernel 4: deterministic final loss ----------------
__global__ void k_loss(float* __restrict__ out) {
    __shared__ float red[256];
    const int tid = threadIdx.x;
    float s = 0.f;
#pragma unroll
    for (int i = 0; i < 32; i++) s += g_part[tid + 256 * i];
    red[tid] = s;
    __syncthreads();
    for (int st = 128; st > 0; st >>= 1) {
        if (tid < st) red[tid] += red[tid + st];
        __syncthreads();
    }
    if (tid == 0)
        out[(size_t)F_ * B_ * D_] = red[0] * (0.25f / (float)(F_ * B_ * D_));
}

extern "C" void kernel_launch(void* const* d_in, const int* in_sizes, int n_in,
                              void* d_out, int out_size) {
    const float* x = (const float*)d_in[0];   // [F,B,D] fp32
    const float* w = (const float*)d_in[1];   // [F,D,K] fp32
    float* out = (float*)d_out;
    (void)in_sizes; (void)n_in; (void)out_size;

    k_prep<<<NB_X + NB_T + NB_W, 256>>>(x, w);

    cudaFuncSetAttribute(k_screen, cudaFuncAttributeMaxDynamicSharedMemorySize, 99328);
    k_screen<<<dim3(B_ / 128, K_ / 128, F_), 256, 99328>>>();

    k_rescore<<<(F_ * B_) / 8, 256>>>(x, out);
    k_loss<<<1, 256>>>(out);
}